// round 5
// baseline (speedup 1.0000x reference)
#include <cuda_runtime.h>

#define B_SZ 16
#define N_PTS 4096
#define HALF_N 2048
#define K_NN 20
#define CO 64
#define STAT_BLOCKS 256
#define NVALS 27
#define CAP 16          // per-lane smem stack capacity (slots)
#define NCHUNK_H 16

// ---------------- scratch (static device allocations, allowed) ----------------
__device__ int                g_idx[B_SZ * N_PTS * K_NN];            // 5.24 MB
__device__ unsigned long long g_pk[2 * B_SZ * N_PTS * K_NN];         // 21 MB keys
__device__ double             g_part[STAT_BLOCKS * NVALS];
__device__ float              g_scale[CO];
__device__ float              g_shift[CO];

// packed f32x2 helpers (sm_100+ PTX)
__device__ __forceinline__ unsigned long long pack2(float lo, float hi) {
    unsigned long long r;
    asm("mov.b64 %0, {%1,%2};" : "=l"(r) : "f"(lo), "f"(hi));
    return r;
}
__device__ __forceinline__ void unpack2(unsigned long long v, float& lo, float& hi) {
    asm("mov.b64 {%0,%1}, %2;" : "=f"(lo), "=f"(hi) : "l"(v));
}
#define FMA2(d, a, b, c) \
    asm("fma.rn.f32x2 %0, %1, %2, %3;" : "=l"(d) : "l"(a), "l"(b), "l"(c))

// float bits -> order-preserving u32 (handles negatives), and inverse
__device__ __forceinline__ unsigned fkey(float f) {
    unsigned b = __float_as_uint(f);
    return b ^ ((unsigned)((int)b >> 31) | 0x80000000u);
}
__device__ __forceinline__ float fkey_inv(unsigned t) {
    unsigned b = (t & 0x80000000u) ? (t ^ 0x80000000u) : ~t;
    return __uint_as_float(b);
}

// =============================================================================
// Kernel 1: per-batch exact KNN over HALF the candidate range per block.
// Sorted top-20 kept as u64 keys (dist_bits<<12 | idx) -> tie handling is
// EXACTLY jax top_k (earlier index wins). Hot loop is branch-free: survivors
// of the stale 20th threshold go to a per-lane conflict-free smem stack via
// predicated st.shared; stacks are replayed at 16 geometric chunk boundaries.
// Overflow (P~1e-4 per lane-chunk) falls back to a deterministic rescan.
// Partial sorted keys for the two halves are merged by kernel 1b.
// =============================================================================
__device__ __forceinline__ void insert20k(unsigned long long k,
                                          unsigned long long (&val)[K_NN]) {
#pragma unroll
    for (int j = 0; j < K_NN; j++) {
        unsigned long long vj = val[j];
        bool lt = k < vj;
        val[j] = lt ? k : vj;     // keep smaller
        k      = lt ? vj : k;     // carry larger
    }
}

__global__ void __launch_bounds__(512, 2)
knn_half_kernel(const float* __restrict__ x) {
    extern __shared__ char smem_raw[];
    float4* pts = (float4*)smem_raw;                        // 2048*16 = 32 KB
    char*   stacks = smem_raw + HALF_N * sizeof(float4);    // 16*CAP*256 = 64 KB

    const int b    = blockIdx.y;
    const int qblk = blockIdx.x >> 1;
    const int half = blockIdx.x & 1;
    const int base = half * HALF_N;                         // candidate offset
    const float* xb = x + (size_t)b * N_PTS * 3;

    // stage this block's candidate half
    for (int i = threadIdx.x; i < HALF_N; i += 512) {
        int m = base + i;
        float x0 = xb[m * 3 + 0], x1 = xb[m * 3 + 1], x2 = xb[m * 3 + 2];
        float sq = fmaf(x0, x0, fmaf(x1, x1, x2 * x2));
        pts[i] = make_float4(x0, x1, x2, sq);
    }
    __syncthreads();

    // query point loaded straight from gmem (may live in the other half)
    const int q = qblk * 512 + threadIdx.x;
    const float* xq = xb + (size_t)q * 3;
    const float qx = __ldg(xq), qy = __ldg(xq + 1), qz = __ldg(xq + 2);
    const float m2x = -2.0f * qx, m2y = -2.0f * qy, m2z = -2.0f * qz;
    const float qw = fmaf(qx, qx, fmaf(qy, qy, qz * qz));

    // per-lane stack addressing (shared address space)
    const unsigned sbase =
        (unsigned)__cvta_generic_to_shared(
            stacks + (size_t)(threadIdx.x >> 5) * (CAP * 256)) +
        (threadIdx.x & 31) * 8;
    const unsigned limit = sbase + CAP * 256;
    unsigned addr = sbase;

    unsigned long long val[K_NN];
#pragma unroll
    for (int j = 0; j < K_NN; j++) val[j] = 0xFFFFFFFFFFFFFFFFull;

    // ---- init: first 20 local candidates, unconditional keyed insert ----
#pragma unroll 2
    for (int i = 0; i < K_NN; i++) {
        float4 p = pts[i];
        float d = fmaf(m2x, p.x, fmaf(m2y, p.y, fmaf(m2z, p.z, p.w))) + qw;
        insert20k(((unsigned long long)fkey(d) << 12) | (unsigned)(base + i), val);
    }
    float v19 = fkey_inv((unsigned)(val[K_NN - 1] >> 12));

    static const short bnd[NCHUNK_H] = {
        27, 36, 48, 64, 85, 114, 152, 203,
        271, 362, 483, 645, 861, 1150, 1535, 2048};

    int lo = K_NN;
#pragma unroll 1
    for (int c = 0; c < NCHUNK_H; c++) {
        const int hi = bnd[c];
        // ---- branch-free scan (local indices) ----
#pragma unroll 2
        for (int i = lo; i < hi; i++) {
            float4 p = pts[i];
            float d = fmaf(m2x, p.x, fmaf(m2y, p.y, fmaf(m2z, p.z, p.w))) + qw;
            asm volatile(
                "{\n\t"
                ".reg .pred p;\n\t"
                "setp.lt.f32 p, %1, %2;\n\t"
                "setp.lt.and.u32 p, %0, %3, p;\n\t"
                "@p st.shared.v2.b32 [%0], {%4, %5};\n\t"
                "@p add.u32 %0, %0, 256;\n\t"
                "}"
                : "+r"(addr)
                : "f"(d), "f"(v19), "r"(limit), "r"(__float_as_int(d)), "r"(i));
        }
        // ---- flush: replay stack (unconditional keyed inserts; too-large
        //      keys are no-ops in insert20k) ----
        const bool ovf = (addr >= limit);
        const unsigned stop = ovf ? sbase : addr;
        for (unsigned pp = sbase; pp < stop; pp += 256) {
            unsigned e0, e1;
            asm volatile("ld.shared.v2.b32 {%0,%1}, [%2];"
                         : "=r"(e0), "=r"(e1) : "r"(pp));
            insert20k(((unsigned long long)fkey(__int_as_float((int)e0)) << 12) |
                      (unsigned)(base + (int)e1), val);
        }
        if (__any_sync(0xFFFFFFFFu, ovf)) {      // rare deterministic fallback
            for (int i = lo; i < hi; i++) {
                float4 p = pts[i];
                float d = fmaf(m2x, p.x, fmaf(m2y, p.y, fmaf(m2z, p.z, p.w))) + qw;
                unsigned long long k =
                    ((unsigned long long)fkey(d) << 12) | (unsigned)(base + i);
                if (ovf && k < val[K_NN - 1]) insert20k(k, val);
            }
        }
        addr = sbase;
        v19 = fkey_inv((unsigned)(val[K_NN - 1] >> 12));
        lo = hi;
    }

    unsigned long long* outp =
        g_pk + ((size_t)(half * B_SZ + b) * N_PTS + q) * K_NN;
#pragma unroll
    for (int j = 0; j < K_NN; j++) outp[j] = val[j];
}

// =============================================================================
// Kernel 1b: merge the two sorted 20-lists per query (u64 keys), emit indices.
// =============================================================================
__global__ void knn_merge_kernel() {
    const int t = blockIdx.x * blockDim.x + threadIdx.x;    // 0..65535
    const unsigned long long* pa = g_pk + (size_t)t * K_NN;
    const unsigned long long* pb =
        g_pk + ((size_t)B_SZ * N_PTS + t) * K_NN;
    int* op = g_idx + (size_t)t * K_NN;

    int i = 0, j = 0;
#pragma unroll
    for (int o = 0; o < K_NN; o++) {
        unsigned long long a = __ldg(pa + i);
        unsigned long long bb = __ldg(pb + j);
        bool ta = a < bb;
        op[o] = (int)((ta ? a : bb) & 0xFFFu);
        i += ta; j += !ta;
    }
}

// =============================================================================
// Kernel 2: fp64 moment accumulation for global BatchNorm statistics.
// h_c(edge) is affine in (xi, xj) -> mean/var need only 27 moments.
// Deterministic: warp shuffle-reduce -> smem -> per-block partial, summed
// serially in finalize.
// =============================================================================
__global__ void stats_kernel(const float* __restrict__ x) {
    const int pt = blockIdx.x * blockDim.x + threadIdx.x;
    const int b = pt >> 12;
    const int gbase = b << 12;

    const float* xr = x + (size_t)pt * 3;
    double di0 = (double)xr[0], di1 = (double)xr[1], di2 = (double)xr[2];

    double sj0 = 0, sj1 = 0, sj2 = 0;
    double jj00 = 0, jj01 = 0, jj02 = 0, jj11 = 0, jj12 = 0, jj22 = 0;
    double ij00 = 0, ij01 = 0, ij02 = 0, ij10 = 0, ij11 = 0, ij12 = 0,
           ij20 = 0, ij21 = 0, ij22 = 0;

    const int* ip = g_idx + (size_t)pt * K_NN;
#pragma unroll 4
    for (int k = 0; k < K_NN; k++) {
        int j = __ldg(ip + k);
        const float* xp = x + (size_t)(gbase + j) * 3;
        double j0 = (double)__ldg(xp + 0);
        double j1 = (double)__ldg(xp + 1);
        double j2 = (double)__ldg(xp + 2);
        sj0 += j0; sj1 += j1; sj2 += j2;
        jj00 += j0 * j0; jj01 += j0 * j1; jj02 += j0 * j2;
        jj11 += j1 * j1; jj12 += j1 * j2; jj22 += j2 * j2;
        ij00 += di0 * j0; ij01 += di0 * j1; ij02 += di0 * j2;
        ij10 += di1 * j0; ij11 += di1 * j1; ij12 += di1 * j2;
        ij20 += di2 * j0; ij21 += di2 * j1; ij22 += di2 * j2;
    }

    double vals[NVALS] = {
        di0, di1, di2,
        di0 * di0, di0 * di1, di0 * di2, di1 * di1, di1 * di2, di2 * di2,
        sj0, sj1, sj2,
        jj00, jj01, jj02, jj11, jj12, jj22,
        ij00, ij01, ij02, ij10, ij11, ij12, ij20, ij21, ij22
    };

    __shared__ double wsum[8][NVALS];
    const int wid = threadIdx.x >> 5;
    const int lid = threadIdx.x & 31;

#pragma unroll
    for (int v = 0; v < NVALS; v++) {
        double s = vals[v];
#pragma unroll
        for (int o = 16; o > 0; o >>= 1) s += __shfl_xor_sync(0xFFFFFFFFu, s, o);
        if (lid == 0) wsum[wid][v] = s;
    }
    __syncthreads();

    if (threadIdx.x < NVALS) {
        double s = 0.0;
#pragma unroll
        for (int w = 0; w < 8; w++) s += wsum[w][threadIdx.x];
        g_part[blockIdx.x * NVALS + threadIdx.x] = s;
    }
}

// =============================================================================
// Kernel 3: finalize BN stats -> per-channel scale/shift (fp64 math).
// =============================================================================
__global__ void finalize_kernel(const float* __restrict__ w1,
                                const float* __restrict__ b1,
                                const float* __restrict__ gamma,
                                const float* __restrict__ beta) {
    __shared__ double S[NVALS];
    if (threadIdx.x < NVALS) {
        double s = 0.0;
        for (int bl = 0; bl < STAT_BLOCKS; bl++) s += g_part[bl * NVALS + threadIdx.x];
        S[threadIdx.x] = s;
    }
    __syncthreads();

    const int c = threadIdx.x;              // 64 threads
    const double M = (double)B_SZ * N_PTS * K_NN;
    const double Kd = (double)K_NN;

    double q0 = (double)w1[3 * CO + c], q1 = (double)w1[4 * CO + c], q2 = (double)w1[5 * CO + c];
    double p0 = (double)w1[0 * CO + c] - q0;
    double p1 = (double)w1[1 * CO + c] - q1;
    double p2 = (double)w1[2 * CO + c] - q2;
    double s_ = (double)b1[c];

    double Si0 = Kd * S[0], Si1 = Kd * S[1], Si2 = Kd * S[2];
    double i00 = Kd * S[3], i01 = Kd * S[4], i02 = Kd * S[5];
    double i11 = Kd * S[6], i12 = Kd * S[7], i22 = Kd * S[8];
    double Sj0 = S[9], Sj1 = S[10], Sj2 = S[11];
    double j00 = S[12], j01 = S[13], j02 = S[14], j11 = S[15], j12 = S[16], j22 = S[17];

    double pSi = p0 * Si0 + p1 * Si1 + p2 * Si2;
    double qSj = q0 * Sj0 + q1 * Sj1 + q2 * Sj2;
    double mean = (pSi + qSj) / M + s_;

    double pMp = p0 * p0 * i00 + p1 * p1 * i11 + p2 * p2 * i22 +
                 2.0 * (p0 * p1 * i01 + p0 * p2 * i02 + p1 * p2 * i12);
    double qMq = q0 * q0 * j00 + q1 * q1 * j11 + q2 * q2 * j22 +
                 2.0 * (q0 * q1 * j01 + q0 * q2 * j02 + q1 * q2 * j12);
    double pMq = p0 * (q0 * S[18] + q1 * S[19] + q2 * S[20]) +
                 p1 * (q0 * S[21] + q1 * S[22] + q2 * S[23]) +
                 p2 * (q0 * S[24] + q1 * S[25] + q2 * S[26]);

    double sumsq = pMp + qMq + 2.0 * pMq + 2.0 * s_ * (pSi + qSj) + M * s_ * s_;
    double var = sumsq / M - mean * mean;
    double rstd = 1.0 / sqrt(var + 1e-5);

    double g = (double)gamma[c];
    g_scale[c] = (float)(g * rstd);
    g_shift[c] = (float)((double)beta[c] - mean * g * rstd);
}

// =============================================================================
// Kernel 4: fused edge-MLP + BN + ReLU + (r @ w2) + max over K.
// One warp per point: 2 output channels per lane. BN unfolded (raw w1/b1,
// then scale/shift). Stage-2 GEMM uses packed fma.rn.f32x2 (FFMA2).
// =============================================================================
__global__ void __launch_bounds__(256, 3)
main_kernel(const float* __restrict__ x,
            const float* __restrict__ w1,
            const float* __restrict__ b1,
            const float* __restrict__ w2,
            const float* __restrict__ b2,
            float* __restrict__ out) {
    extern __shared__ float sm[];
    float* w2s = sm;               // 64*64
    float* rt  = sm + CO * CO;     // 8 warps * 64 * 20

    for (int i = threadIdx.x; i < CO * CO; i += blockDim.x) w2s[i] = w2[i];
    __syncthreads();

    const int w = threadIdx.x >> 5;
    const int l = threadIdx.x & 31;
    const int pt = blockIdx.x * 8 + w;
    float* rw = rt + w * (CO * K_NN);

    const int ca = l, cb = l + 32;

    float w1a[6], w1b[6];
#pragma unroll
    for (int r = 0; r < 6; r++) {
        w1a[r] = __ldg(w1 + r * CO + ca);
        w1b[r] = __ldg(w1 + r * CO + cb);
    }
    const float b1a = __ldg(b1 + ca), b1b = __ldg(b1 + cb);
    const float sca = g_scale[ca], scb = g_scale[cb];
    const float sha = g_shift[ca], shb = g_shift[cb];

    const int b = pt >> 12;
    const int gbase = b << 12;
    const float* xr = x + (size_t)pt * 3;
    const float xi0 = __ldg(xr), xi1 = __ldg(xr + 1), xi2 = __ldg(xr + 2);
    const int* ip = g_idx + (size_t)pt * K_NN;

    // ---- stage 1: r[c][k] = relu(scale*h + shift) ----
#pragma unroll 4
    for (int k = 0; k < K_NN; k++) {
        int j = __ldg(ip + k);
        const float* xp = x + (size_t)(gbase + j) * 3;
        float d0 = __ldg(xp)     - xi0;
        float d1 = __ldg(xp + 1) - xi1;
        float d2 = __ldg(xp + 2) - xi2;

        float ha = b1a;
        ha = fmaf(xi0, w1a[0], ha); ha = fmaf(xi1, w1a[1], ha); ha = fmaf(xi2, w1a[2], ha);
        ha = fmaf(d0,  w1a[3], ha); ha = fmaf(d1,  w1a[4], ha); ha = fmaf(d2,  w1a[5], ha);
        float hb = b1b;
        hb = fmaf(xi0, w1b[0], hb); hb = fmaf(xi1, w1b[1], hb); hb = fmaf(xi2, w1b[2], hb);
        hb = fmaf(d0,  w1b[3], hb); hb = fmaf(d1,  w1b[4], hb); hb = fmaf(d2,  w1b[5], hb);

        rw[ca * K_NN + k] = fmaxf(fmaf(ha, sca, sha), 0.0f);
        rw[cb * K_NN + k] = fmaxf(fmaf(hb, scb, shb), 0.0f);
    }
    __syncwarp();

    // ---- stage 2: packed FFMA2 GEMM, acc[i] holds k=(2i, 2i+1) ----
    unsigned long long acca[K_NN / 2], accb[K_NN / 2];
#pragma unroll
    for (int i = 0; i < K_NN / 2; i++) { acca[i] = 0ULL; accb[i] = 0ULL; }

#pragma unroll 4
    for (int c = 0; c < CO; c++) {
        float wa = w2s[c * CO + ca];
        float wb = w2s[c * CO + cb];
        unsigned long long wa2 = pack2(wa, wa);
        unsigned long long wb2 = pack2(wb, wb);
        const ulonglong2* r2 = (const ulonglong2*)(rw + c * K_NN);
#pragma unroll
        for (int t = 0; t < 5; t++) {
            ulonglong2 rv = r2[t];
            FMA2(acca[2 * t],     rv.x, wa2, acca[2 * t]);
            FMA2(acca[2 * t + 1], rv.y, wa2, acca[2 * t + 1]);
            FMA2(accb[2 * t],     rv.x, wb2, accb[2 * t]);
            FMA2(accb[2 * t + 1], rv.y, wb2, accb[2 * t + 1]);
        }
    }

    float ma = -3.402823466e38f, mb = -3.402823466e38f;
#pragma unroll
    for (int i = 0; i < K_NN / 2; i++) {
        float a0, a1, b0, b1v;
        unpack2(acca[i], a0, a1);
        unpack2(accb[i], b0, b1v);
        ma = fmaxf(ma, fmaxf(a0, a1));
        mb = fmaxf(mb, fmaxf(b0, b1v));
    }

    out[(size_t)pt * CO + ca] = ma + __ldg(b2 + ca);
    out[(size_t)pt * CO + cb] = mb + __ldg(b2 + cb);
}

// =============================================================================
extern "C" void kernel_launch(void* const* d_in, const int* in_sizes, int n_in,
                              void* d_out, int out_size) {
    const float* x     = (const float*)d_in[0];
    // d_in[1] = batch indices (implied by layout; unused)
    const float* w1    = (const float*)d_in[2];
    const float* b1    = (const float*)d_in[3];
    const float* gamma = (const float*)d_in[4];
    const float* beta  = (const float*)d_in[5];
    const float* w2    = (const float*)d_in[6];
    const float* b2    = (const float*)d_in[7];
    float* out = (float*)d_out;

    const int knn_smem  = HALF_N * sizeof(float4) + 16 * CAP * 256;     // 96 KB
    const int main_smem = (CO * CO + 8 * CO * K_NN) * sizeof(float);    // 56 KB

    cudaFuncSetAttribute(knn_half_kernel, cudaFuncAttributeMaxDynamicSharedMemorySize, knn_smem);
    cudaFuncSetAttribute(main_kernel,     cudaFuncAttributeMaxDynamicSharedMemorySize, main_smem);

    knn_half_kernel<<<dim3(16, B_SZ), 512, knn_smem>>>(x);
    knn_merge_kernel<<<(B_SZ * N_PTS) / 256, 256>>>();
    stats_kernel<<<STAT_BLOCKS, 256>>>(x);
    finalize_kernel<<<1, 64>>>(w1, b1, gamma, beta);
    main_kernel<<<(B_SZ * N_PTS) / 8, 256, main_smem>>>(x, w1, b1, w2, b2, out);
}

// round 6
// speedup vs baseline: 1.4282x; 1.4282x over previous
#include <cuda_runtime.h>

#define B_SZ 16
#define N_PTS 4096
#define K_NN 20
#define CO 64
#define KNN_BLOCKS 128
#define NVALS 27
#define CAP 24          // per-lane smem stack capacity (slots)
#define NCHUNK 16

// ---------------- scratch (static device allocations, allowed) ----------------
__device__ int    g_idx[B_SZ * N_PTS * K_NN];       // 5.24 MB
__device__ double g_part[KNN_BLOCKS * NVALS];
__device__ float  g_scale[CO];
__device__ float  g_shift[CO];

// packed f32x2 helpers (sm_100+ PTX)
__device__ __forceinline__ unsigned long long pack2(float lo, float hi) {
    unsigned long long r;
    asm("mov.b64 %0, {%1,%2};" : "=l"(r) : "f"(lo), "f"(hi));
    return r;
}
__device__ __forceinline__ void unpack2(unsigned long long v, float& lo, float& hi) {
    asm("mov.b64 {%0,%1}, %2;" : "=f"(lo), "=f"(hi) : "l"(v));
}
#define FMA2(d, a, b, c) \
    asm("fma.rn.f32x2 %0, %1, %2, %3;" : "=l"(d) : "l"(a), "l"(b), "l"(c))

// float bits -> order-preserving u32 key (handles negatives)
__device__ __forceinline__ unsigned fkey(float f) {
    unsigned b = __float_as_uint(f);
    return b ^ ((unsigned)((int)b >> 31) | 0x80000000u);
}
__device__ __forceinline__ float fkey_inv(unsigned t) {
    unsigned b = (t & 0x80000000u) ? (t ^ 0x80000000u) : ~t;
    return __uint_as_float(b);
}

// sorted top-20 as u64 keys (dist_key<<12 | idx): EXACT jax top_k semantics
__device__ __forceinline__ void insert20k(unsigned long long k,
                                          unsigned long long (&val)[K_NN]) {
#pragma unroll
    for (int j = 0; j < K_NN; j++) {
        unsigned long long vj = val[j];
        bool lt = k < vj;
        val[j] = lt ? k : vj;     // keep smaller
        k      = lt ? vj : k;     // carry larger
    }
}

// =============================================================================
// Kernel 1: per-batch exact KNN (one query/thread, 4096 candidates in smem)
// FUSED with fp64 BatchNorm moment accumulation (epilogue).
//
// Distances use the exact __fmul/__fadd form that matched the reference
// (rel_err 3e-7 in R1):  t = (qx*px + qy*py) + qz*pz ;  d = (qw+pw) - 2*t.
// Hot loop is branch-free: survivors of the stale 20th-distance threshold go
// to a per-lane conflict-free smem stack via predicated st.shared; stacks are
// replayed into the sorted u64-key top-20 at 16 geometric chunk boundaries.
// Stack overflow (P ~ 1e-8/lane/chunk) -> deterministic rescan of the chunk.
//
// Epilogue: per-point 27 BN moments in fp32 (20 terms each), aggregated in
// fp64 via warp shuffle + block reduce -> g_part (deterministic).
// =============================================================================
__global__ void __launch_bounds__(512, 1)
knn_stats_kernel(const float* __restrict__ x) {
    extern __shared__ char smem_raw[];
    float4* pts = (float4*)smem_raw;                       // 64 KB
    char*   stacks = smem_raw + N_PTS * sizeof(float4);    // 16*CAP*256 = 96 KB

    const int b    = blockIdx.y;
    const int qblk = blockIdx.x;
    const float* xb = x + (size_t)b * N_PTS * 3;

    for (int i = threadIdx.x; i < N_PTS; i += 512) {
        float x0 = xb[i * 3 + 0], x1 = xb[i * 3 + 1], x2 = xb[i * 3 + 2];
        float sq = __fadd_rn(__fadd_rn(__fmul_rn(x0, x0), __fmul_rn(x1, x1)),
                             __fmul_rn(x2, x2));
        pts[i] = make_float4(x0, x1, x2, sq);
    }
    __syncthreads();

    const int q = qblk * 512 + threadIdx.x;
    const float4 qp = pts[q];

    // per-lane stack addressing (shared address space)
    const unsigned sbase =
        (unsigned)__cvta_generic_to_shared(
            stacks + (size_t)(threadIdx.x >> 5) * (CAP * 256)) +
        (threadIdx.x & 31) * 8;
    const unsigned limit = sbase + CAP * 256;
    unsigned addr = sbase;

    unsigned long long val[K_NN];
#pragma unroll
    for (int j = 0; j < K_NN; j++) val[j] = 0xFFFFFFFFFFFFFFFFull;

    // ---- init: first 20 candidates, unconditional keyed insert ----
#pragma unroll 2
    for (int m = 0; m < K_NN; m++) {
        float4 p = pts[m];
        float t = __fadd_rn(__fadd_rn(__fmul_rn(qp.x, p.x), __fmul_rn(qp.y, p.y)),
                            __fmul_rn(qp.z, p.z));
        float d = __fsub_rn(__fadd_rn(qp.w, p.w), __fmul_rn(2.0f, t));
        insert20k(((unsigned long long)fkey(d) << 12) | (unsigned)m, val);
    }
    float v19 = fkey_inv((unsigned)(val[K_NN - 1] >> 12));

    static const short bnd[NCHUNK] = {
        28, 39, 55, 77, 108, 151, 211, 296,
        414, 580, 812, 1137, 1592, 2229, 3120, 4096};

    int lo = K_NN;
#pragma unroll 1
    for (int c = 0; c < NCHUNK; c++) {
        const int hi = bnd[c];
        // ---- branch-free scan ----
#pragma unroll 4
        for (int m = lo; m < hi; m++) {
            float4 p = pts[m];
            float t = __fadd_rn(__fadd_rn(__fmul_rn(qp.x, p.x), __fmul_rn(qp.y, p.y)),
                                __fmul_rn(qp.z, p.z));
            float d = __fsub_rn(__fadd_rn(qp.w, p.w), __fmul_rn(2.0f, t));
            asm volatile(
                "{\n\t"
                ".reg .pred p;\n\t"
                "setp.lt.f32 p, %1, %2;\n\t"
                "setp.lt.and.u32 p, %0, %3, p;\n\t"
                "@p st.shared.v2.b32 [%0], {%4, %5};\n\t"
                "@p add.u32 %0, %0, 256;\n\t"
                "}"
                : "+r"(addr)
                : "f"(d), "f"(v19), "r"(limit), "r"(__float_as_int(d)), "r"(m));
        }
        // ---- flush: replay stack into sorted top-20 (keyed) ----
        const bool ovf = (addr >= limit);
        const unsigned stop = ovf ? sbase : addr;
        for (unsigned pp = sbase; pp < stop; pp += 256) {
            unsigned e0, e1;
            asm volatile("ld.shared.v2.b32 {%0,%1}, [%2];"
                         : "=r"(e0), "=r"(e1) : "r"(pp));
            unsigned long long k =
                ((unsigned long long)fkey(__int_as_float((int)e0)) << 12) | e1;
            if (k < val[K_NN - 1]) insert20k(k, val);
        }
        if (__any_sync(0xFFFFFFFFu, ovf)) {      // rare deterministic fallback
            for (int m = lo; m < hi; m++) {
                float4 p = pts[m];
                float t = __fadd_rn(__fadd_rn(__fmul_rn(qp.x, p.x), __fmul_rn(qp.y, p.y)),
                                    __fmul_rn(qp.z, p.z));
                float d = __fsub_rn(__fadd_rn(qp.w, p.w), __fmul_rn(2.0f, t));
                unsigned long long k =
                    ((unsigned long long)fkey(d) << 12) | (unsigned)m;
                if (ovf && k < val[K_NN - 1]) insert20k(k, val);
            }
        }
        addr = sbase;
        v19 = fkey_inv((unsigned)(val[K_NN - 1] >> 12));
        lo = hi;
    }

    // ---- write indices ----
    int* op = g_idx + ((size_t)(b * N_PTS) + q) * K_NN;
#pragma unroll
    for (int j = 0; j < K_NN; j++) op[j] = (int)(val[j] & 0xFFFu);

    // ================= fused BN moment epilogue =================
    // fp32 per-point accumulation (20 terms), fp64 aggregation.
    float sj0 = 0, sj1 = 0, sj2 = 0;
    float jj00 = 0, jj01 = 0, jj02 = 0, jj11 = 0, jj12 = 0, jj22 = 0;
    float ij00 = 0, ij01 = 0, ij02 = 0, ij10 = 0, ij11 = 0, ij12 = 0,
          ij20 = 0, ij21 = 0, ij22 = 0;
#pragma unroll
    for (int j = 0; j < K_NN; j++) {
        float4 p = pts[val[j] & 0xFFFu];
        sj0 += p.x; sj1 += p.y; sj2 += p.z;
        jj00 = fmaf(p.x, p.x, jj00); jj01 = fmaf(p.x, p.y, jj01);
        jj02 = fmaf(p.x, p.z, jj02); jj11 = fmaf(p.y, p.y, jj11);
        jj12 = fmaf(p.y, p.z, jj12); jj22 = fmaf(p.z, p.z, jj22);
        ij00 = fmaf(qp.x, p.x, ij00); ij01 = fmaf(qp.x, p.y, ij01);
        ij02 = fmaf(qp.x, p.z, ij02); ij10 = fmaf(qp.y, p.x, ij10);
        ij11 = fmaf(qp.y, p.y, ij11); ij12 = fmaf(qp.y, p.z, ij12);
        ij20 = fmaf(qp.z, p.x, ij20); ij21 = fmaf(qp.z, p.y, ij21);
        ij22 = fmaf(qp.z, p.z, ij22);
    }

    double vals[NVALS] = {
        (double)qp.x, (double)qp.y, (double)qp.z,
        (double)qp.x * qp.x, (double)qp.x * qp.y, (double)qp.x * qp.z,
        (double)qp.y * qp.y, (double)qp.y * qp.z, (double)qp.z * qp.z,
        (double)sj0, (double)sj1, (double)sj2,
        (double)jj00, (double)jj01, (double)jj02,
        (double)jj11, (double)jj12, (double)jj22,
        (double)ij00, (double)ij01, (double)ij02,
        (double)ij10, (double)ij11, (double)ij12,
        (double)ij20, (double)ij21, (double)ij22
    };

    __syncthreads();                       // stacks no longer needed
    double* wsum = (double*)stacks;        // [16][NVALS]
    const int wid = threadIdx.x >> 5;
    const int lid = threadIdx.x & 31;
#pragma unroll
    for (int v = 0; v < NVALS; v++) {
        double s = vals[v];
#pragma unroll
        for (int o = 16; o > 0; o >>= 1) s += __shfl_xor_sync(0xFFFFFFFFu, s, o);
        if (lid == 0) wsum[wid * NVALS + v] = s;
    }
    __syncthreads();
    if (threadIdx.x < NVALS) {
        double s = 0.0;
#pragma unroll
        for (int w = 0; w < 16; w++) s += wsum[w * NVALS + threadIdx.x];
        g_part[(blockIdx.y * gridDim.x + blockIdx.x) * NVALS + threadIdx.x] = s;
    }
}

// =============================================================================
// Kernel 2: finalize BN stats -> per-channel scale/shift (fp64 math).
// 27 warps reduce the 128 partials in parallel; first 64 threads finish.
// =============================================================================
__global__ void __launch_bounds__(864, 1)
finalize_kernel(const float* __restrict__ w1,
                const float* __restrict__ b1,
                const float* __restrict__ gamma,
                const float* __restrict__ beta) {
    __shared__ double S[NVALS];
    const int wid = threadIdx.x >> 5;
    const int lid = threadIdx.x & 31;
    if (wid < NVALS) {
        double s = 0.0;
#pragma unroll
        for (int r = 0; r < KNN_BLOCKS / 32; r++)
            s += g_part[(r * 32 + lid) * NVALS + wid];
#pragma unroll
        for (int o = 16; o > 0; o >>= 1) s += __shfl_xor_sync(0xFFFFFFFFu, s, o);
        if (lid == 0) S[wid] = s;
    }
    __syncthreads();
    if (threadIdx.x >= CO) return;

    const int c = threadIdx.x;
    const double M = (double)B_SZ * N_PTS * K_NN;
    const double Kd = (double)K_NN;

    double q0 = (double)w1[3 * CO + c], q1 = (double)w1[4 * CO + c], q2 = (double)w1[5 * CO + c];
    double p0 = (double)w1[0 * CO + c] - q0;
    double p1 = (double)w1[1 * CO + c] - q1;
    double p2 = (double)w1[2 * CO + c] - q2;
    double s_ = (double)b1[c];

    double Si0 = Kd * S[0], Si1 = Kd * S[1], Si2 = Kd * S[2];
    double i00 = Kd * S[3], i01 = Kd * S[4], i02 = Kd * S[5];
    double i11 = Kd * S[6], i12 = Kd * S[7], i22 = Kd * S[8];
    double Sj0 = S[9], Sj1 = S[10], Sj2 = S[11];
    double j00 = S[12], j01 = S[13], j02 = S[14], j11 = S[15], j12 = S[16], j22 = S[17];

    double pSi = p0 * Si0 + p1 * Si1 + p2 * Si2;
    double qSj = q0 * Sj0 + q1 * Sj1 + q2 * Sj2;
    double mean = (pSi + qSj) / M + s_;

    double pMp = p0 * p0 * i00 + p1 * p1 * i11 + p2 * p2 * i22 +
                 2.0 * (p0 * p1 * i01 + p0 * p2 * i02 + p1 * p2 * i12);
    double qMq = q0 * q0 * j00 + q1 * q1 * j11 + q2 * q2 * j22 +
                 2.0 * (q0 * q1 * j01 + q0 * q2 * j02 + q1 * q2 * j12);
    double pMq = p0 * (q0 * S[18] + q1 * S[19] + q2 * S[20]) +
                 p1 * (q0 * S[21] + q1 * S[22] + q2 * S[23]) +
                 p2 * (q0 * S[24] + q1 * S[25] + q2 * S[26]);

    double sumsq = pMp + qMq + 2.0 * pMq + 2.0 * s_ * (pSi + qSj) + M * s_ * s_;
    double var = sumsq / M - mean * mean;
    double rstd = 1.0 / sqrt(var + 1e-5);

    double g = (double)gamma[c];
    g_scale[c] = (float)(g * rstd);
    g_shift[c] = (float)((double)beta[c] - mean * g * rstd);
}

// =============================================================================
// Kernel 3: fused edge-MLP + BN + ReLU + (r @ w2) + max over K.
// One warp per point: 2 output channels per lane. BN unfolded (raw w1/b1,
// then scale/shift). Stage-2 GEMM uses packed fma.rn.f32x2; (wa,wb) loaded
// as one float2 from a repacked w2.
// =============================================================================
__global__ void __launch_bounds__(256, 3)
main_kernel(const float* __restrict__ x,
            const float* __restrict__ w1,
            const float* __restrict__ b1,
            const float* __restrict__ w2,
            const float* __restrict__ b2,
            float* __restrict__ out) {
    extern __shared__ float sm[];
    float2* w2p = (float2*)sm;             // [64][32] float2 = 64*64 floats
    float*  rt  = sm + CO * CO;            // 8 warps * 64 * 20

    for (int i = threadIdx.x; i < CO * 32; i += blockDim.x) {
        int c = i >> 5, l = i & 31;
        w2p[i] = make_float2(w2[c * CO + l], w2[c * CO + l + 32]);
    }
    __syncthreads();

    const int w = threadIdx.x >> 5;
    const int l = threadIdx.x & 31;
    const int pt = blockIdx.x * 8 + w;
    float* rw = rt + w * (CO * K_NN);

    const int ca = l, cb = l + 32;

    float w1a[6], w1b[6];
#pragma unroll
    for (int r = 0; r < 6; r++) {
        w1a[r] = __ldg(w1 + r * CO + ca);
        w1b[r] = __ldg(w1 + r * CO + cb);
    }
    const float b1a = __ldg(b1 + ca), b1b = __ldg(b1 + cb);
    const float sca = g_scale[ca], scb = g_scale[cb];
    const float sha = g_shift[ca], shb = g_shift[cb];

    const int b = pt >> 12;
    const int gbase = b << 12;
    const float* xr = x + (size_t)pt * 3;
    const float xi0 = __ldg(xr), xi1 = __ldg(xr + 1), xi2 = __ldg(xr + 2);
    const int* ip = g_idx + (size_t)pt * K_NN;

    // ---- stage 1: r[c][k] = relu(scale*h + shift) ----
#pragma unroll 4
    for (int k = 0; k < K_NN; k++) {
        int j = __ldg(ip + k);
        const float* xp = x + (size_t)(gbase + j) * 3;
        float d0 = __ldg(xp)     - xi0;
        float d1 = __ldg(xp + 1) - xi1;
        float d2 = __ldg(xp + 2) - xi2;

        float ha = b1a;
        ha = fmaf(xi0, w1a[0], ha); ha = fmaf(xi1, w1a[1], ha); ha = fmaf(xi2, w1a[2], ha);
        ha = fmaf(d0,  w1a[3], ha); ha = fmaf(d1,  w1a[4], ha); ha = fmaf(d2,  w1a[5], ha);
        float hb = b1b;
        hb = fmaf(xi0, w1b[0], hb); hb = fmaf(xi1, w1b[1], hb); hb = fmaf(xi2, w1b[2], hb);
        hb = fmaf(d0,  w1b[3], hb); hb = fmaf(d1,  w1b[4], hb); hb = fmaf(d2,  w1b[5], hb);

        rw[ca * K_NN + k] = fmaxf(fmaf(ha, sca, sha), 0.0f);
        rw[cb * K_NN + k] = fmaxf(fmaf(hb, scb, shb), 0.0f);
    }
    __syncwarp();

    // ---- stage 2: packed FFMA2 GEMM, acc[i] holds k=(2i, 2i+1) ----
    unsigned long long acca[K_NN / 2], accb[K_NN / 2];
#pragma unroll
    for (int i = 0; i < K_NN / 2; i++) { acca[i] = 0ULL; accb[i] = 0ULL; }

#pragma unroll 4
    for (int c = 0; c < CO; c++) {
        float2 wab = w2p[c * 32 + l];
        unsigned long long wa2 = pack2(wab.x, wab.x);
        unsigned long long wb2 = pack2(wab.y, wab.y);
        const ulonglong2* r2 = (const ulonglong2*)(rw + c * K_NN);
#pragma unroll
        for (int t = 0; t < 5; t++) {
            ulonglong2 rv = r2[t];
            FMA2(acca[2 * t],     rv.x, wa2, acca[2 * t]);
            FMA2(acca[2 * t + 1], rv.y, wa2, acca[2 * t + 1]);
            FMA2(accb[2 * t],     rv.x, wb2, accb[2 * t]);
            FMA2(accb[2 * t + 1], rv.y, wb2, accb[2 * t + 1]);
        }
    }

    float ma = -3.402823466e38f, mb = -3.402823466e38f;
#pragma unroll
    for (int i = 0; i < K_NN / 2; i++) {
        float a0, a1, b0, b1v;
        unpack2(acca[i], a0, a1);
        unpack2(accb[i], b0, b1v);
        ma = fmaxf(ma, fmaxf(a0, a1));
        mb = fmaxf(mb, fmaxf(b0, b1v));
    }

    out[(size_t)pt * CO + ca] = ma + __ldg(b2 + ca);
    out[(size_t)pt * CO + cb] = mb + __ldg(b2 + cb);
}

// =============================================================================
extern "C" void kernel_launch(void* const* d_in, const int* in_sizes, int n_in,
                              void* d_out, int out_size) {
    const float* x     = (const float*)d_in[0];
    // d_in[1] = batch indices (implied by layout; unused)
    const float* w1    = (const float*)d_in[2];
    const float* b1    = (const float*)d_in[3];
    const float* gamma = (const float*)d_in[4];
    const float* beta  = (const float*)d_in[5];
    const float* w2    = (const float*)d_in[6];
    const float* b2    = (const float*)d_in[7];
    float* out = (float*)d_out;

    const int knn_smem  = N_PTS * sizeof(float4) + 16 * CAP * 256;      // 160 KB
    const int main_smem = (CO * CO + 8 * CO * K_NN) * sizeof(float);    // 56 KB

    cudaFuncSetAttribute(knn_stats_kernel, cudaFuncAttributeMaxDynamicSharedMemorySize, knn_smem);
    cudaFuncSetAttribute(main_kernel,      cudaFuncAttributeMaxDynamicSharedMemorySize, main_smem);

    knn_stats_kernel<<<dim3(8, B_SZ), 512, knn_smem>>>(x);
    finalize_kernel<<<1, 864>>>(w1, b1, gamma, beta);
    main_kernel<<<(B_SZ * N_PTS) / 8, 256, main_smem>>>(x, w1, b1, w2, b2, out);
}

// round 7
// speedup vs baseline: 1.5808x; 1.1068x over previous
#include <cuda_runtime.h>

#define B_SZ 16
#define N_PTS 4096
#define K_NN 20
#define CO 64
#define KNN_BLOCKS 128
#define NVALS 27
#define CAP 32          // per-lane smem stack capacity (4B slots)
#define NCHUNK 16
#define SLACK 2e-3f

// ---------------- scratch (static device allocations, allowed) ----------------
__device__ int    g_idx[B_SZ * N_PTS * K_NN];       // 5.24 MB
__device__ double g_part[KNN_BLOCKS * NVALS];
__device__ float  g_scale[CO];
__device__ float  g_shift[CO];

// packed f32x2 helpers (sm_100+ PTX)
__device__ __forceinline__ unsigned long long pack2(float lo, float hi) {
    unsigned long long r;
    asm("mov.b64 %0, {%1,%2};" : "=l"(r) : "f"(lo), "f"(hi));
    return r;
}
__device__ __forceinline__ void unpack2(unsigned long long v, float& lo, float& hi) {
    asm("mov.b64 {%0,%1}, %2;" : "=f"(lo), "=f"(hi) : "l"(v));
}
#define FMA2(d, a, b, c) \
    asm("fma.rn.f32x2 %0, %1, %2, %3;" : "=l"(d) : "l"(a), "l"(b), "l"(c))

// float bits -> order-preserving u32 key (handles negatives)
__device__ __forceinline__ unsigned fkey(float f) {
    unsigned b = __float_as_uint(f);
    return b ^ ((unsigned)((int)b >> 31) | 0x80000000u);
}
__device__ __forceinline__ float fkey_inv(unsigned t) {
    unsigned b = (t & 0x80000000u) ? (t ^ 0x80000000u) : ~t;
    return __uint_as_float(b);
}

// sorted top-20 as u64 keys (dist_key<<12 | idx): EXACT jax top_k semantics
__device__ __forceinline__ void insert20k(unsigned long long k,
                                          unsigned long long (&val)[K_NN]) {
#pragma unroll
    for (int j = 0; j < K_NN; j++) {
        unsigned long long vj = val[j];
        bool lt = k < vj;
        val[j] = lt ? k : vj;     // keep smaller
        k      = lt ? vj : k;     // carry larger
    }
}

// exact reference-rounding distance from scaled point (px2=-2x etc.)
__device__ __forceinline__ float exact_d(float qx, float qy, float qz, float qw,
                                         float4 p) {
    float px = __fmul_rn(-0.5f, p.x);   // exact
    float py = __fmul_rn(-0.5f, p.y);
    float pz = __fmul_rn(-0.5f, p.z);
    float t = __fadd_rn(__fadd_rn(__fmul_rn(qx, px), __fmul_rn(qy, py)),
                        __fmul_rn(qz, pz));
    return __fsub_rn(__fadd_rn(qw, p.w), __fmul_rn(2.0f, t));
}

// =============================================================================
// Kernel 1: per-batch exact KNN (one query/thread, 4096 candidates in smem)
// FUSED with fp64 BatchNorm moment accumulation (epilogue).
//
// Candidates stored pre-scaled (-2x,-2y,-2z,||x||^2) so the screening test is
// 3 FFMA: d' = fma(px2,qx, fma(py2,qy, fma(pz2,qz, pw))). Screen threshold
// tau' = v19 - qw + SLACK (slack >> rounding divergence of d' vs exact d).
// Survivors push only their index (predicated st.shared.b32, no branch) to a
// per-lane conflict-free stack; at 16 geometric chunk boundaries the stack
// replays: EXACT reference-rounded distance recomputed, u64 keyed insert
// (dist_bits<<12|idx) preserves jax top_k tie semantics exactly.
// Overflow -> deterministic exact rescan of the chunk.
// =============================================================================
__global__ void __launch_bounds__(512, 1)
knn_stats_kernel(const float* __restrict__ x) {
    extern __shared__ char smem_raw[];
    float4* pts = (float4*)smem_raw;                       // 64 KB
    char*   stacks = smem_raw + N_PTS * sizeof(float4);    // 16*CAP*128 = 64 KB

    const int b    = blockIdx.y;
    const int qblk = blockIdx.x;
    const float* xb = x + (size_t)b * N_PTS * 3;

    for (int i = threadIdx.x; i < N_PTS; i += 512) {
        float x0 = xb[i * 3 + 0], x1 = xb[i * 3 + 1], x2 = xb[i * 3 + 2];
        float sq = __fadd_rn(__fadd_rn(__fmul_rn(x0, x0), __fmul_rn(x1, x1)),
                             __fmul_rn(x2, x2));
        pts[i] = make_float4(__fmul_rn(-2.0f, x0), __fmul_rn(-2.0f, x1),
                             __fmul_rn(-2.0f, x2), sq);
    }
    __syncthreads();

    const int q = qblk * 512 + threadIdx.x;
    const float4 qp = pts[q];
    const float qx = __fmul_rn(-0.5f, qp.x);
    const float qy = __fmul_rn(-0.5f, qp.y);
    const float qz = __fmul_rn(-0.5f, qp.z);
    const float qw = qp.w;

    // per-lane stack addressing (shared address space), 4B slots, 128B stride
    const unsigned sbase =
        (unsigned)__cvta_generic_to_shared(
            stacks + (size_t)(threadIdx.x >> 5) * (CAP * 128)) +
        (threadIdx.x & 31) * 4;
    const unsigned limit = sbase + CAP * 128;
    unsigned addr = sbase;

    unsigned long long val[K_NN];
#pragma unroll
    for (int j = 0; j < K_NN; j++) val[j] = 0xFFFFFFFFFFFFFFFFull;

    // ---- init: first 20 candidates, unconditional exact keyed insert ----
#pragma unroll 2
    for (int m = 0; m < K_NN; m++) {
        float d = exact_d(qx, qy, qz, qw, pts[m]);
        insert20k(((unsigned long long)fkey(d) << 12) | (unsigned)m, val);
    }
    float tau = fkey_inv((unsigned)(val[K_NN - 1] >> 12)) - qw + SLACK;

    static const short bnd[NCHUNK] = {
        28, 39, 55, 77, 108, 151, 211, 296,
        414, 580, 812, 1137, 1592, 2229, 3120, 4096};

    int lo = K_NN;
#pragma unroll 1
    for (int c = 0; c < NCHUNK; c++) {
        const int hi = bnd[c];
        // ---- branch-free screening scan: 3 FFMA + predicated push ----
#pragma unroll 4
        for (int m = lo; m < hi; m++) {
            float4 p = pts[m];
            float ds = fmaf(p.x, qx, fmaf(p.y, qy, fmaf(p.z, qz, p.w)));
            asm volatile(
                "{\n\t"
                ".reg .pred p;\n\t"
                "setp.lt.f32 p, %1, %2;\n\t"
                "setp.lt.and.u32 p, %0, %3, p;\n\t"
                "@p st.shared.b32 [%0], %4;\n\t"
                "@p add.u32 %0, %0, 128;\n\t"
                "}"
                : "+r"(addr)
                : "f"(ds), "f"(tau), "r"(limit), "r"(m));
        }
        // ---- flush: exact recompute + keyed insert ----
        const bool ovf = (addr >= limit);
        const unsigned stop = ovf ? sbase : addr;
        for (unsigned pp = sbase; pp < stop; pp += 128) {
            unsigned m;
            asm volatile("ld.shared.b32 %0, [%1];" : "=r"(m) : "r"(pp));
            float d = exact_d(qx, qy, qz, qw, pts[m]);
            unsigned long long k = ((unsigned long long)fkey(d) << 12) | m;
            if (k < val[K_NN - 1]) insert20k(k, val);
        }
        if (__any_sync(0xFFFFFFFFu, ovf)) {      // rare deterministic fallback
            for (int m = lo; m < hi; m++) {
                float d = exact_d(qx, qy, qz, qw, pts[m]);
                unsigned long long k =
                    ((unsigned long long)fkey(d) << 12) | (unsigned)m;
                if (ovf && k < val[K_NN - 1]) insert20k(k, val);
            }
        }
        addr = sbase;
        tau = fkey_inv((unsigned)(val[K_NN - 1] >> 12)) - qw + SLACK;
        lo = hi;
    }

    // ---- write indices ----
    int* op = g_idx + ((size_t)(b * N_PTS) + q) * K_NN;
#pragma unroll
    for (int j = 0; j < K_NN; j++) op[j] = (int)(val[j] & 0xFFFu);

    // ================= fused BN moment epilogue =================
    // fp32 per-point accumulation (20 terms), fp64 aggregation.
    // True coords recovered exactly: x = -0.5 * stored.
    const float qix = qx, qiy = qy, qiz = qz;
    float sj0 = 0, sj1 = 0, sj2 = 0;
    float jj00 = 0, jj01 = 0, jj02 = 0, jj11 = 0, jj12 = 0, jj22 = 0;
    float ij00 = 0, ij01 = 0, ij02 = 0, ij10 = 0, ij11 = 0, ij12 = 0,
          ij20 = 0, ij21 = 0, ij22 = 0;
#pragma unroll
    for (int j = 0; j < K_NN; j++) {
        float4 p = pts[val[j] & 0xFFFu];
        float pxx = -0.5f * p.x, pyy = -0.5f * p.y, pzz = -0.5f * p.z;
        sj0 += pxx; sj1 += pyy; sj2 += pzz;
        jj00 = fmaf(pxx, pxx, jj00); jj01 = fmaf(pxx, pyy, jj01);
        jj02 = fmaf(pxx, pzz, jj02); jj11 = fmaf(pyy, pyy, jj11);
        jj12 = fmaf(pyy, pzz, jj12); jj22 = fmaf(pzz, pzz, jj22);
        ij00 = fmaf(qix, pxx, ij00); ij01 = fmaf(qix, pyy, ij01);
        ij02 = fmaf(qix, pzz, ij02); ij10 = fmaf(qiy, pxx, ij10);
        ij11 = fmaf(qiy, pyy, ij11); ij12 = fmaf(qiy, pzz, ij12);
        ij20 = fmaf(qiz, pxx, ij20); ij21 = fmaf(qiz, pyy, ij21);
        ij22 = fmaf(qiz, pzz, ij22);
    }

    double vals[NVALS] = {
        (double)qix, (double)qiy, (double)qiz,
        (double)qix * qix, (double)qix * qiy, (double)qix * qiz,
        (double)qiy * qiy, (double)qiy * qiz, (double)qiz * qiz,
        (double)sj0, (double)sj1, (double)sj2,
        (double)jj00, (double)jj01, (double)jj02,
        (double)jj11, (double)jj12, (double)jj22,
        (double)ij00, (double)ij01, (double)ij02,
        (double)ij10, (double)ij11, (double)ij12,
        (double)ij20, (double)ij21, (double)ij22
    };

    __syncthreads();                       // stacks no longer needed
    double* wsum = (double*)stacks;        // [16][NVALS]
    const int wid = threadIdx.x >> 5;
    const int lid = threadIdx.x & 31;
#pragma unroll
    for (int v = 0; v < NVALS; v++) {
        double s = vals[v];
#pragma unroll
        for (int o = 16; o > 0; o >>= 1) s += __shfl_xor_sync(0xFFFFFFFFu, s, o);
        if (lid == 0) wsum[wid * NVALS + v] = s;
    }
    __syncthreads();
    if (threadIdx.x < NVALS) {
        double s = 0.0;
#pragma unroll
        for (int w = 0; w < 16; w++) s += wsum[w * NVALS + threadIdx.x];
        g_part[(blockIdx.y * gridDim.x + blockIdx.x) * NVALS + threadIdx.x] = s;
    }
}

// =============================================================================
// Kernel 2: finalize BN stats -> per-channel scale/shift (fp64 math).
// =============================================================================
__global__ void __launch_bounds__(864, 1)
finalize_kernel(const float* __restrict__ w1,
                const float* __restrict__ b1,
                const float* __restrict__ gamma,
                const float* __restrict__ beta) {
    __shared__ double S[NVALS];
    const int wid = threadIdx.x >> 5;
    const int lid = threadIdx.x & 31;
    if (wid < NVALS) {
        double s = 0.0;
#pragma unroll
        for (int r = 0; r < KNN_BLOCKS / 32; r++)
            s += g_part[(r * 32 + lid) * NVALS + wid];
#pragma unroll
        for (int o = 16; o > 0; o >>= 1) s += __shfl_xor_sync(0xFFFFFFFFu, s, o);
        if (lid == 0) S[wid] = s;
    }
    __syncthreads();
    if (threadIdx.x >= CO) return;

    const int c = threadIdx.x;
    const double M = (double)B_SZ * N_PTS * K_NN;
    const double Kd = (double)K_NN;

    double q0 = (double)w1[3 * CO + c], q1 = (double)w1[4 * CO + c], q2 = (double)w1[5 * CO + c];
    double p0 = (double)w1[0 * CO + c] - q0;
    double p1 = (double)w1[1 * CO + c] - q1;
    double p2 = (double)w1[2 * CO + c] - q2;
    double s_ = (double)b1[c];

    double Si0 = Kd * S[0], Si1 = Kd * S[1], Si2 = Kd * S[2];
    double i00 = Kd * S[3], i01 = Kd * S[4], i02 = Kd * S[5];
    double i11 = Kd * S[6], i12 = Kd * S[7], i22 = Kd * S[8];
    double Sj0 = S[9], Sj1 = S[10], Sj2 = S[11];
    double j00 = S[12], j01 = S[13], j02 = S[14], j11 = S[15], j12 = S[16], j22 = S[17];

    double pSi = p0 * Si0 + p1 * Si1 + p2 * Si2;
    double qSj = q0 * Sj0 + q1 * Sj1 + q2 * Sj2;
    double mean = (pSi + qSj) / M + s_;

    double pMp = p0 * p0 * i00 + p1 * p1 * i11 + p2 * p2 * i22 +
                 2.0 * (p0 * p1 * i01 + p0 * p2 * i02 + p1 * p2 * i12);
    double qMq = q0 * q0 * j00 + q1 * q1 * j11 + q2 * q2 * j22 +
                 2.0 * (q0 * q1 * j01 + q0 * q2 * j02 + q1 * q2 * j12);
    double pMq = p0 * (q0 * S[18] + q1 * S[19] + q2 * S[20]) +
                 p1 * (q0 * S[21] + q1 * S[22] + q2 * S[23]) +
                 p2 * (q0 * S[24] + q1 * S[25] + q2 * S[26]);

    double sumsq = pMp + qMq + 2.0 * pMq + 2.0 * s_ * (pSi + qSj) + M * s_ * s_;
    double var = sumsq / M - mean * mean;
    double rstd = 1.0 / sqrt(var + 1e-5);

    double g = (double)gamma[c];
    g_scale[c] = (float)(g * rstd);
    g_shift[c] = (float)((double)beta[c] - mean * g * rstd);
}

// =============================================================================
// Kernel 3: fused edge-MLP + BN + ReLU + (r @ w2) + max over K.
// One warp per point, 2 channels/lane. Stage-1 algebra: h = xi.(w0-w3) +
// xj.w3 + b1 -> per-point base + 3 FFMA per k per channel. BN unfolded.
// Stage-2 GEMM uses packed fma.rn.f32x2.
// =============================================================================
__global__ void __launch_bounds__(256, 3)
main_kernel(const float* __restrict__ x,
            const float* __restrict__ w1,
            const float* __restrict__ b1,
            const float* __restrict__ w2,
            const float* __restrict__ b2,
            float* __restrict__ out) {
    extern __shared__ float sm[];
    float2* w2p = (float2*)sm;             // [64][32] float2
    float*  rt  = sm + CO * CO;            // 8 warps * 64 * 20

    for (int i = threadIdx.x; i < CO * 32; i += blockDim.x) {
        int c = i >> 5, l = i & 31;
        w2p[i] = make_float2(w2[c * CO + l], w2[c * CO + l + 32]);
    }
    __syncthreads();

    const int w = threadIdx.x >> 5;
    const int l = threadIdx.x & 31;
    const int pt = blockIdx.x * 8 + w;
    float* rw = rt + w * (CO * K_NN);

    const int ca = l, cb = l + 32;

    float wja[3], wjb[3], wia[3], wib[3];
#pragma unroll
    for (int r = 0; r < 3; r++) {
        float a0 = __ldg(w1 + r * CO + ca);
        float a3 = __ldg(w1 + (r + 3) * CO + ca);
        float b0 = __ldg(w1 + r * CO + cb);
        float b3 = __ldg(w1 + (r + 3) * CO + cb);
        wja[r] = a3; wjb[r] = b3;
        wia[r] = a0 - a3; wib[r] = b0 - b3;
    }
    const float b1a = __ldg(b1 + ca), b1b = __ldg(b1 + cb);
    const float sca = g_scale[ca], scb = g_scale[cb];
    const float sha = g_shift[ca], shb = g_shift[cb];

    const int b = pt >> 12;
    const int gbase = b << 12;
    const float* xr = x + (size_t)pt * 3;
    const float xi0 = __ldg(xr), xi1 = __ldg(xr + 1), xi2 = __ldg(xr + 2);
    const int* ip = g_idx + (size_t)pt * K_NN;

    // per-point bases: h = base + xj . wj
    const float basea = fmaf(xi2, wia[2], fmaf(xi1, wia[1], fmaf(xi0, wia[0], b1a)));
    const float baseb = fmaf(xi2, wib[2], fmaf(xi1, wib[1], fmaf(xi0, wib[0], b1b)));

    // ---- stage 1: r[c][k] = relu(scale*h + shift) ----
#pragma unroll 4
    for (int k = 0; k < K_NN; k++) {
        int j = __ldg(ip + k);
        const float* xp = x + (size_t)(gbase + j) * 3;
        float j0 = __ldg(xp), j1 = __ldg(xp + 1), j2 = __ldg(xp + 2);

        float ha = fmaf(j2, wja[2], fmaf(j1, wja[1], fmaf(j0, wja[0], basea)));
        float hb = fmaf(j2, wjb[2], fmaf(j1, wjb[1], fmaf(j0, wjb[0], baseb)));

        rw[ca * K_NN + k] = fmaxf(fmaf(ha, sca, sha), 0.0f);
        rw[cb * K_NN + k] = fmaxf(fmaf(hb, scb, shb), 0.0f);
    }
    __syncwarp();

    // ---- stage 2: packed FFMA2 GEMM, acc[i] holds k=(2i, 2i+1) ----
    unsigned long long acca[K_NN / 2], accb[K_NN / 2];
#pragma unroll
    for (int i = 0; i < K_NN / 2; i++) { acca[i] = 0ULL; accb[i] = 0ULL; }

#pragma unroll 4
    for (int c = 0; c < CO; c++) {
        float2 wab = w2p[c * 32 + l];
        unsigned long long wa2 = pack2(wab.x, wab.x);
        unsigned long long wb2 = pack2(wab.y, wab.y);
        const ulonglong2* r2 = (const ulonglong2*)(rw + c * K_NN);
#pragma unroll
        for (int t = 0; t < 5; t++) {
            ulonglong2 rv = r2[t];
            FMA2(acca[2 * t],     rv.x, wa2, acca[2 * t]);
            FMA2(acca[2 * t + 1], rv.y, wa2, acca[2 * t + 1]);
            FMA2(accb[2 * t],     rv.x, wb2, accb[2 * t]);
            FMA2(accb[2 * t + 1], rv.y, wb2, accb[2 * t + 1]);
        }
    }

    float ma = -3.402823466e38f, mb = -3.402823466e38f;
#pragma unroll
    for (int i = 0; i < K_NN / 2; i++) {
        float a0, a1, b0, b1v;
        unpack2(acca[i], a0, a1);
        unpack2(accb[i], b0, b1v);
        ma = fmaxf(ma, fmaxf(a0, a1));
        mb = fmaxf(mb, fmaxf(b0, b1v));
    }

    out[(size_t)pt * CO + ca] = ma + __ldg(b2 + ca);
    out[(size_t)pt * CO + cb] = mb + __ldg(b2 + cb);
}

// =============================================================================
extern "C" void kernel_launch(void* const* d_in, const int* in_sizes, int n_in,
                              void* d_out, int out_size) {
    const float* x     = (const float*)d_in[0];
    // d_in[1] = batch indices (implied by layout; unused)
    const float* w1    = (const float*)d_in[2];
    const float* b1    = (const float*)d_in[3];
    const float* gamma = (const float*)d_in[4];
    const float* beta  = (const float*)d_in[5];
    const float* w2    = (const float*)d_in[6];
    const float* b2    = (const float*)d_in[7];
    float* out = (float*)d_out;

    const int knn_smem  = N_PTS * sizeof(float4) + 16 * CAP * 128;      // 128 KB
    const int main_smem = (CO * CO + 8 * CO * K_NN) * sizeof(float);    // 56 KB

    cudaFuncSetAttribute(knn_stats_kernel, cudaFuncAttributeMaxDynamicSharedMemorySize, knn_smem);
    cudaFuncSetAttribute(main_kernel,      cudaFuncAttributeMaxDynamicSharedMemorySize, main_smem);

    knn_stats_kernel<<<dim3(8, B_SZ), 512, knn_smem>>>(x);
    finalize_kernel<<<1, 864>>>(w1, b1, gamma, beta);
    main_kernel<<<(B_SZ * N_PTS) / 8, 256, main_smem>>>(x, w1, b1, w2, b2, out);
}